// round 6
// baseline (speedup 1.0000x reference)
#include <cuda_runtime.h>

// Problem constants (fixed by the reference)
#define Bdim 2
#define Ndim 4096
#define FIN  256
#define FO   64
#define NH   4
#define ROWS (Bdim * Ndim)

#define TI 32
#define TJ 32

// Scratch (no allocation allowed -> __device__ globals)
__device__ float g_X [ROWS * FO];   // (B,N,64) = h @ W
__device__ float g_el[ROWS * NH];   // (B,N,4)
__device__ float g_er[ROWS * NH];   // (B,N,4)

// ---------------- packed f32x2 helpers (Blackwell FFMA2 path) ----------------
__device__ __forceinline__ unsigned long long pk2(float a, float b) {
    unsigned long long r;
    asm("mov.b64 %0, {%1, %2};"
        : "=l"(r) : "r"(__float_as_uint(a)), "r"(__float_as_uint(b)));
    return r;
}
__device__ __forceinline__ float2 upk2(unsigned long long v) {
    unsigned int lo, hi;
    asm("mov.b64 {%0, %1}, %2;" : "=r"(lo), "=r"(hi) : "l"(v));
    return make_float2(__uint_as_float(lo), __uint_as_float(hi));
}
__device__ __forceinline__ unsigned long long fma2(unsigned long long a,
                                                   unsigned long long b,
                                                   unsigned long long c) {
    unsigned long long d;
    asm("fma.rn.f32x2 %0, %1, %2, %3;" : "=l"(d) : "l"(a), "l"(b), "l"(c));
    return d;
}

// ---------------- Kernel A: X = h @ W  (8192x256 @ 256x64) ----------------
// 64x64 output tile per block, 256 threads, 4x4 micro-tile, K chunks of 32.
__global__ __launch_bounds__(256) void k_gemm_xw(const float* __restrict__ h,
                                                 const float* __restrict__ W) {
    __shared__ float sh[64][33];  // h tile [row][k], padded
    __shared__ float sw[32][64];  // W tile [k][f]

    const int tid  = threadIdx.x;
    const int tx   = tid & 15;
    const int ty   = tid >> 4;
    const int row0 = blockIdx.x * 64;

    float acc[4][4];
#pragma unroll
    for (int i = 0; i < 4; i++)
#pragma unroll
        for (int j = 0; j < 4; j++) acc[i][j] = 0.0f;

    for (int k0 = 0; k0 < FIN; k0 += 32) {
        __syncthreads();
#pragma unroll
        for (int m = 0; m < 8; m++) {
            int idx = tid + 256 * m;
            sh[idx >> 5][idx & 31] =
                h[(size_t)(row0 + (idx >> 5)) * FIN + k0 + (idx & 31)];
            sw[idx >> 6][idx & 63] = W[(size_t)(k0 + (idx >> 6)) * FO + (idx & 63)];
        }
        __syncthreads();
#pragma unroll
        for (int kk = 0; kk < 32; kk++) {
            float a[4];
#pragma unroll
            for (int i = 0; i < 4; i++) a[i] = sh[ty * 4 + i][kk];
            float4 bb = *(const float4*)&sw[kk][tx * 4];
#pragma unroll
            for (int i = 0; i < 4; i++) {
                acc[i][0] = fmaf(a[i], bb.x, acc[i][0]);
                acc[i][1] = fmaf(a[i], bb.y, acc[i][1]);
                acc[i][2] = fmaf(a[i], bb.z, acc[i][2]);
                acc[i][3] = fmaf(a[i], bb.w, acc[i][3]);
            }
        }
    }
#pragma unroll
    for (int i = 0; i < 4; i++) {
        float4 v = make_float4(acc[i][0], acc[i][1], acc[i][2], acc[i][3]);
        *(float4*)&g_X[(size_t)(row0 + ty * 4 + i) * FO + tx * 4] = v;
    }
}

// ---------------- Kernel B: el/er = X @ Wl^T, X @ Wr^T ----------------
// One warp per row; each lane holds 2 features; shuffle-reduce 8 dots.
__global__ __launch_bounds__(128) void k_coef(const float* __restrict__ Wl,
                                              const float* __restrict__ Wr) {
    const int row  = blockIdx.x * 4 + (threadIdx.x >> 5);
    const int lane = threadIdx.x & 31;
    float2 x2 = *(const float2*)&g_X[(size_t)row * FO + lane * 2];
#pragma unroll
    for (int hh = 0; hh < NH; hh++) {
        float2 wl = *(const float2*)&Wl[hh * FO + lane * 2];
        float v = x2.x * wl.x + x2.y * wl.y;
#pragma unroll
        for (int o = 16; o > 0; o >>= 1) v += __shfl_xor_sync(0xffffffffu, v, o);
        float2 wr = *(const float2*)&Wr[hh * FO + lane * 2];
        float u = x2.x * wr.x + x2.y * wr.y;
#pragma unroll
        for (int o = 16; o > 0; o >>= 1) u += __shfl_xor_sync(0xffffffffu, u, o);
        if (lane == 0) {
            g_el[row * NH + hh] = v;
            g_er[row * NH + hh] = u;
        }
    }
}

// ---------------- Kernel C: fused masked-softmax attention + PV ----------------
// One block per (b, 32-row i-tile). Loop over 32-col j-tiles:
//   phase B: P[ti*4+h][tj] = adj ? exp(leaky(el+er)) : 0   (duplicated f32x2)
//   phase C: acc[128 rows x 64 cols] += P @ Xs             (fma.rn.f32x2)
// Denominator accumulated in registers during phase B; epilogue: /den + bias + ELU.
__global__ __launch_bounds__(256, 2) void k_attn(const int* __restrict__ adj,
                                                 const float* __restrict__ bias,
                                                 float* __restrict__ out) {
    __shared__ unsigned long long Ps[TI * NH][TJ + 1];  // 33792 B, p duplicated
    __shared__ float Xs[TJ][FO];                        // 8192 B
    __shared__ int   As[TI][TJ];                        // 4096 B
    __shared__ float elS[TI][NH];                       // 512 B
    __shared__ float erS[TJ][NH];                       // 512 B
    __shared__ float denS[TI * NH];                     // 512 B

    const int tid = threadIdx.x;
    const int b   = blockIdx.x >> 7;           // N/TI = 128 tiles per batch
    const int i0  = (blockIdx.x & 127) * TI;

    if (tid < TI * NH)
        elS[tid >> 2][tid & 3] =
            g_el[(size_t)(b * Ndim + i0 + (tid >> 2)) * NH + (tid & 3)];
    __syncthreads();

    // phase-B mapping: pairs of threads per (ti, head); each covers 16 tj's
    const int pairi = tid >> 1;          // == ti*4 + hh == P row index
    const int ti    = pairi >> 2;
    const int hh    = pairi & 3;
    const int half  = tid & 1;
    const float elv = elS[ti][hh];
    float den = 0.0f;

    // phase-C mapping: 8 rows x 4 cols per thread
    const int tx = tid & 15;
    const int ty = tid >> 4;

    unsigned long long acc0[8], acc1[8];
#pragma unroll
    for (int m = 0; m < 8; m++) { acc0[m] = 0ull; acc1[m] = 0ull; }

    const size_t adjRow = ((size_t)b * Ndim + i0) * Ndim;
    const float* Xbase  = g_X + (size_t)b * Ndim * FO;
    const float* erB    = g_er + (size_t)b * Ndim * NH;

    for (int j0 = 0; j0 < Ndim; j0 += TJ) {
        __syncthreads();  // previous phase C done before overwriting tiles
#pragma unroll
        for (int m = 0; m < 4; m++) {
            int idx = tid + 256 * m;
            As[idx >> 5][idx & 31] =
                adj[adjRow + (size_t)(idx >> 5) * Ndim + j0 + (idx & 31)];
        }
#pragma unroll
        for (int m = 0; m < 2; m++) {
            int idx = tid + 256 * m;
            *(float4*)&Xs[idx >> 4][(idx & 15) * 4] =
                *(const float4*)&Xbase[(size_t)(j0 + (idx >> 4)) * FO + (idx & 15) * 4];
        }
        if (tid < TJ * NH)
            erS[tid >> 2][tid & 3] = erB[(size_t)(j0 + (tid >> 2)) * NH + (tid & 3)];
        __syncthreads();

        // ---- phase B: scores -> exp -> mask; den kept in registers ----
#pragma unroll
        for (int t = 0; t < 16; t++) {
            int tj = half * 16 + t;
            float s = elv + erS[tj][hh];
            s = fmaxf(s, 0.2f * s);                  // leaky_relu, slope 0.2
            float p = As[ti][tj] ? __expf(s) : 0.0f;
            den += p;
            Ps[pairi][tj] = pk2(p, p);
        }
        __syncthreads();

        // ---- phase C: acc += P @ Xs via packed f32x2 FMAs ----
#pragma unroll 4
        for (int k = 0; k < TJ; k++) {
            float4 xk = *(const float4*)&Xs[k][tx * 4];
            unsigned long long x01 = pk2(xk.x, xk.y);
            unsigned long long x23 = pk2(xk.z, xk.w);
#pragma unroll
            for (int m = 0; m < 8; m++) {
                unsigned long long p2 = Ps[ty + 16 * m][k];
                acc0[m] = fma2(p2, x01, acc0[m]);
                acc1[m] = fma2(p2, x23, acc1[m]);
            }
        }
    }

    // combine the two half-denominators (adjacent lanes), publish
    den += __shfl_xor_sync(0xffffffffu, den, 1);
    if (half == 0) denS[pairi] = den;
    __syncthreads();

    const float4 bv = *(const float4*)&bias[tx * 4];
    float* outB = out + (size_t)(b * Ndim + i0) * (NH * FO);
#pragma unroll
    for (int m = 0; m < 8; m++) {
        int r = ty + 16 * m;
        float inv = 1.0f / denS[r];
        float2 a0 = upk2(acc0[m]);
        float2 a1 = upk2(acc1[m]);
        float v0 = fmaf(a0.x, inv, bv.x);
        float v1 = fmaf(a0.y, inv, bv.y);
        float v2 = fmaf(a1.x, inv, bv.z);
        float v3 = fmaf(a1.y, inv, bv.w);
        v0 = v0 > 0.0f ? v0 : expm1f(v0);            // ELU (alpha=1)
        v1 = v1 > 0.0f ? v1 : expm1f(v1);
        v2 = v2 > 0.0f ? v2 : expm1f(v2);
        v3 = v3 > 0.0f ? v3 : expm1f(v3);
        *(float4*)&outB[(size_t)r * FO + tx * 4] = make_float4(v0, v1, v2, v3);
    }
}

// ---------------- launch ----------------
extern "C" void kernel_launch(void* const* d_in, const int* in_sizes, int n_in,
                              void* d_out, int out_size) {
    const int*   adj = (const int*)  d_in[0];  // (B,N,N) int32
    const float* h   = (const float*)d_in[1];  // (B,N,256)
    const float* W   = (const float*)d_in[2];  // (256,64)
    const float* Wl  = (const float*)d_in[3];  // (4,64)
    const float* Wr  = (const float*)d_in[4];  // (4,64)
    const float* bia = (const float*)d_in[5];  // (64,)
    float* out = (float*)d_out;                // (B,N,256)

    k_gemm_xw<<<ROWS / 64, 256>>>(h, W);
    k_coef<<<ROWS / 4, 128>>>(Wl, Wr);
    k_attn<<<Bdim * (Ndim / TI), 256>>>(adj, bia, out);
}

// round 7
// speedup vs baseline: 2.6104x; 2.6104x over previous
#include <cuda_runtime.h>
#include <cuda_bf16.h>

// Problem constants (fixed by the reference)
#define Bdim 2
#define Ndim 4096
#define FIN  256
#define FO   64
#define NH   4
#define ROWS (Bdim * Ndim)   // 8192

#define TI 32               // i-rows per block
#define TJ 32               // j-cols per tile

// -------- device scratch (no allocation allowed) --------
__device__ float        g_X   [ROWS * FO];          // (B,N,64) = h @ W
__device__ float2       g_elEF[ROWS * NH];          // {exp(el), exp(0.2*el)}
__device__ float2       g_erEF[ROWS * NH];          // {exp(er), exp(0.2*er)}
__device__ __nv_bfloat16 g_XTh[ROWS * FO];          // X^T hi, [b][n(64)][j(4096)]
__device__ __nv_bfloat16 g_XTl[ROWS * FO];          // X^T lo
__device__ unsigned      g_mask[ROWS * (Ndim / 32)];// adjacency bitmask [row][jword]

// -------- small helpers --------
__device__ __forceinline__ unsigned pack_bf16x2(float lo, float hi) {
    unsigned r;
    asm("cvt.rn.bf16x2.f32 %0, %1, %2;" : "=r"(r) : "f"(hi), "f"(lo));
    return r;
}
__device__ __forceinline__ float bf16lo_f(unsigned v) { return __uint_as_float(v << 16); }
__device__ __forceinline__ float bf16hi_f(unsigned v) { return __uint_as_float(v & 0xffff0000u); }

__device__ __forceinline__ void mma_bf16(float* c, unsigned a0, unsigned a1,
                                         unsigned a2, unsigned a3,
                                         unsigned b0, unsigned b1) {
    asm volatile(
        "mma.sync.aligned.m16n8k16.row.col.f32.bf16.bf16.f32 "
        "{%0,%1,%2,%3}, {%4,%5,%6,%7}, {%8,%9}, {%0,%1,%2,%3};"
        : "+f"(c[0]), "+f"(c[1]), "+f"(c[2]), "+f"(c[3])
        : "r"(a0), "r"(a1), "r"(a2), "r"(a3), "r"(b0), "r"(b1));
}

// ---------------- Kernel A: X = h @ W ----------------
__global__ __launch_bounds__(256) void k_gemm_xw(const float* __restrict__ h,
                                                 const float* __restrict__ W) {
    __shared__ float sh[64][33];
    __shared__ float sw[32][64];
    const int tid  = threadIdx.x;
    const int tx   = tid & 15;
    const int ty   = tid >> 4;
    const int row0 = blockIdx.x * 64;

    float acc[4][4];
#pragma unroll
    for (int i = 0; i < 4; i++)
#pragma unroll
        for (int j = 0; j < 4; j++) acc[i][j] = 0.0f;

    for (int k0 = 0; k0 < FIN; k0 += 32) {
        __syncthreads();
#pragma unroll
        for (int m = 0; m < 8; m++) {
            int idx = tid + 256 * m;
            sh[idx >> 5][idx & 31] =
                h[(size_t)(row0 + (idx >> 5)) * FIN + k0 + (idx & 31)];
            sw[idx >> 6][idx & 63] = W[(size_t)(k0 + (idx >> 6)) * FO + (idx & 63)];
        }
        __syncthreads();
#pragma unroll
        for (int kk = 0; kk < 32; kk++) {
            float a[4];
#pragma unroll
            for (int i = 0; i < 4; i++) a[i] = sh[ty * 4 + i][kk];
            float4 bb = *(const float4*)&sw[kk][tx * 4];
#pragma unroll
            for (int i = 0; i < 4; i++) {
                acc[i][0] = fmaf(a[i], bb.x, acc[i][0]);
                acc[i][1] = fmaf(a[i], bb.y, acc[i][1]);
                acc[i][2] = fmaf(a[i], bb.z, acc[i][2]);
                acc[i][3] = fmaf(a[i], bb.w, acc[i][3]);
            }
        }
    }
#pragma unroll
    for (int i = 0; i < 4; i++)
        *(float4*)&g_X[(size_t)(row0 + ty * 4 + i) * FO + tx * 4] =
            make_float4(acc[i][0], acc[i][1], acc[i][2], acc[i][3]);
}

// ---------------- Kernel B: attention coefficients -> exp pairs ----------------
__global__ __launch_bounds__(128) void k_coef(const float* __restrict__ Wl,
                                              const float* __restrict__ Wr) {
    const int row  = blockIdx.x * 4 + (threadIdx.x >> 5);
    const int lane = threadIdx.x & 31;
    float2 x2 = *(const float2*)&g_X[(size_t)row * FO + lane * 2];
#pragma unroll
    for (int hh = 0; hh < NH; hh++) {
        float2 wl = *(const float2*)&Wl[hh * FO + lane * 2];
        float v = x2.x * wl.x + x2.y * wl.y;
#pragma unroll
        for (int o = 16; o > 0; o >>= 1) v += __shfl_xor_sync(0xffffffffu, v, o);
        float2 wr = *(const float2*)&Wr[hh * FO + lane * 2];
        float u = x2.x * wr.x + x2.y * wr.y;
#pragma unroll
        for (int o = 16; o > 0; o >>= 1) u += __shfl_xor_sync(0xffffffffu, u, o);
        if (lane == 0) {
            g_elEF[row * NH + hh] = make_float2(__expf(v), __expf(0.2f * v));
            g_erEF[row * NH + hh] = make_float2(__expf(u), __expf(0.2f * u));
        }
    }
}

// ---------------- Kernel C: transpose + bf16 hi/lo split of X ----------------
// g_XTh/g_XTl[(b*64+n)*4096 + j], 64 j-rows per block.
__global__ __launch_bounds__(256) void k_split() {
    __shared__ float ts[64][65];
    const int tid = threadIdx.x;
    const int r0  = blockIdx.x * 64;               // global row block (j index incl. batch)
#pragma unroll
    for (int m = 0; m < 16; m++) {
        int idx = tid + 256 * m;
        ts[idx >> 6][idx & 63] = g_X[(size_t)(r0 + (idx >> 6)) * FO + (idx & 63)];
    }
    __syncthreads();
    const int n    = tid >> 2;        // 0..63 feature
    const int part = tid & 3;         // 16 j's each
    const int b    = r0 >> 12;
    const int jloc = r0 & 4095;
    size_t base = ((size_t)(b * 64 + n) * Ndim + jloc + part * 16);
#pragma unroll
    for (int jj = 0; jj < 16; jj += 2) {
        float v0 = ts[part * 16 + jj][n];
        float v1 = ts[part * 16 + jj + 1][n];
        unsigned hpack = pack_bf16x2(v0, v1);
        float r0f = v0 - bf16lo_f(hpack);
        float r1f = v1 - bf16hi_f(hpack);
        unsigned lpack = pack_bf16x2(r0f, r1f);
        *(unsigned*)((char*)g_XTh + (base + jj) * 2) = hpack;
        *(unsigned*)((char*)g_XTl + (base + jj) * 2) = lpack;
    }
}

// ---------------- Kernel D: pack adjacency to bitmasks ----------------
__global__ __launch_bounds__(256) void k_pack(const int* __restrict__ adj) {
    const int lane = threadIdx.x & 31;
    const int wgl  = (blockIdx.x * 8) + (threadIdx.x >> 5);  // global warp id, 8192 warps
#pragma unroll 4
    for (int it = 0; it < 128; it++) {
        int word = wgl + it * 8192;
        int v = adj[(size_t)word * 32 + lane];
        unsigned m = __ballot_sync(0xffffffffu, v != 0);
        if (lane == 0) g_mask[word] = m;
    }
}

// ---------------- Kernel E: fused masked-softmax attention + PV (bf16 3-pass MMA) ----
// Block: 256 threads = 8 warps; P logical [128 rows = h*32+i][32 j], warp w owns
// rows 16w..16w+15 (h = w>>1, i base (w&1)*16). Per j-tile: each thread computes
// its 8 A-fragment P values in registers (no smem for P), splits to bf16 hi/lo,
// and runs 3 mma passes per (n-tile,k-tile) into fp32 accumulators.
#define XS_STRIDE 80   // bytes per n-row in Xs (32 bf16 = 64B data + pad); conflict-free
__global__ __launch_bounds__(256) void k_attn(const float* __restrict__ bias,
                                              float* __restrict__ out) {
    __shared__ __align__(16) unsigned char sXh[64 * XS_STRIDE];
    __shared__ __align__(16) unsigned char sXl[64 * XS_STRIDE];
    __shared__ float2 erS[32 * 5];   // [j][h], stride 5 (pad) -> conflict-free

    const int tid  = threadIdx.x;
    const int w    = tid >> 5;
    const int lane = tid & 31;
    const int g    = lane >> 2;      // 0..7
    const int q    = lane & 3;       // 0..3
    const int q2   = q * 2;

    const int bb = blockIdx.x >> 7;
    const int i0 = (blockIdx.x & 127) * TI;
    const int hh = w >> 1;
    const int iA = i0 + (w & 1) * 16 + g;        // rows iA and iA+8

    // per-row constants
    const float2 efA = g_elEF[((bb << 12) + iA) * NH + hh];
    const float2 efB = g_elEF[((bb << 12) + iA + 8) * NH + hh];
    const unsigned* mrowA = &g_mask[(size_t)((bb << 12) + iA) * 128];
    const unsigned* mrowB = &g_mask[(size_t)((bb << 12) + iA + 8) * 128];

    float acc[8][4];
#pragma unroll
    for (int n = 0; n < 8; n++)
#pragma unroll
        for (int k = 0; k < 4; k++) acc[n][k] = 0.0f;
    float den0 = 0.0f, den1 = 0.0f;

    const __nv_bfloat16* XTh = g_XTh + (size_t)bb * 64 * Ndim;
    const __nv_bfloat16* XTl = g_XTl + (size_t)bb * 64 * Ndim;
    const float2* erB = g_erEF + (size_t)(bb << 12) * NH;

    // staging mapping: thread -> (n-row, 16B chunk)
    const int sn = tid >> 2;
    const int sp = tid & 3;

    for (int jt = 0; jt < Ndim / TJ; jt++) {
        const int j0 = jt * TJ;
        __syncthreads();
        // stage X tiles (bf16, transposed: [n][j] rows of 64B)
        {
            size_t src = ((size_t)sn * Ndim + j0 + sp * 8) * 2;  // bytes
            *(uint4*)(sXh + sn * XS_STRIDE + sp * 16) = *(const uint4*)((const char*)XTh + src);
            *(uint4*)(sXl + sn * XS_STRIDE + sp * 16) = *(const uint4*)((const char*)XTl + src);
        }
        // stage er exp-pairs
        if (tid < 128) {
            int j = tid >> 2, hx = tid & 3;
            erS[j * 5 + hx] = erB[(j0 + j) * NH + hx];
        }
        __syncthreads();

        const unsigned mwA = mrowA[jt];
        const unsigned mwB = mrowB[jt];

#pragma unroll
        for (int kt = 0; kt < 2; kt++) {
            // my 4 columns this k-tile: q2, q2+1, q2+8, q2+9 (local to 16-wide kt)
            const int cb = kt * 16 + q2;
            float2 e0 = erS[(cb)     * 5 + hh];
            float2 e1 = erS[(cb + 1) * 5 + hh];
            float2 e2 = erS[(cb + 8) * 5 + hh];
            float2 e3 = erS[(cb + 9) * 5 + hh];

            unsigned msA = mwA >> cb;
            unsigned msB = mwB >> cb;

            float pA0 = (msA & 1u)   ? fmaxf(efA.x * e0.x, efA.y * e0.y) : 0.0f;
            float pA1 = (msA & 2u)   ? fmaxf(efA.x * e1.x, efA.y * e1.y) : 0.0f;
            float pA2 = (msA & 256u) ? fmaxf(efA.x * e2.x, efA.y * e2.y) : 0.0f;
            float pA3 = (msA & 512u) ? fmaxf(efA.x * e3.x, efA.y * e3.y) : 0.0f;
            float pB0 = (msB & 1u)   ? fmaxf(efB.x * e0.x, efB.y * e0.y) : 0.0f;
            float pB1 = (msB & 2u)   ? fmaxf(efB.x * e1.x, efB.y * e1.y) : 0.0f;
            float pB2 = (msB & 256u) ? fmaxf(efB.x * e2.x, efB.y * e2.y) : 0.0f;
            float pB3 = (msB & 512u) ? fmaxf(efB.x * e3.x, efB.y * e3.y) : 0.0f;

            den0 += (pA0 + pA1) + (pA2 + pA3);
            den1 += (pB0 + pB1) + (pB2 + pB3);

            // A fragments (m16k16): a0:(g, c0,c1) a1:(g+8, c0,c1) a2:(g, c2,c3) a3:(g+8, c2,c3)
            unsigned aH0 = pack_bf16x2(pA0, pA1);
            unsigned aH1 = pack_bf16x2(pB0, pB1);
            unsigned aH2 = pack_bf16x2(pA2, pA3);
            unsigned aH3 = pack_bf16x2(pB2, pB3);
            unsigned aL0 = pack_bf16x2(pA0 - bf16lo_f(aH0), pA1 - bf16hi_f(aH0));
            unsigned aL1 = pack_bf16x2(pB0 - bf16lo_f(aH1), pB1 - bf16hi_f(aH1));
            unsigned aL2 = pack_bf16x2(pA2 - bf16lo_f(aH2), pA3 - bf16hi_f(aH2));
            unsigned aL3 = pack_bf16x2(pB2 - bf16lo_f(aH3), pB3 - bf16hi_f(aH3));

            const int boff = g * XS_STRIDE + kt * 32 + q * 4;
#pragma unroll
            for (int nt = 0; nt < 8; nt++) {
                const int o = nt * 8 * XS_STRIDE + boff;
                unsigned bh0 = *(const unsigned*)(sXh + o);
                unsigned bh1 = *(const unsigned*)(sXh + o + 16);
                unsigned bl0 = *(const unsigned*)(sXl + o);
                unsigned bl1 = *(const unsigned*)(sXl + o + 16);
                mma_bf16(acc[nt], aH0, aH1, aH2, aH3, bh0, bh1);
                mma_bf16(acc[nt], aH0, aH1, aH2, aH3, bl0, bl1);
                mma_bf16(acc[nt], aL0, aL1, aL2, aL3, bh0, bh1);
            }
        }
    }

    // reduce denominators across the 4 lanes of each row group
    den0 += __shfl_xor_sync(0xffffffffu, den0, 1);
    den0 += __shfl_xor_sync(0xffffffffu, den0, 2);
    den1 += __shfl_xor_sync(0xffffffffu, den1, 1);
    den1 += __shfl_xor_sync(0xffffffffu, den1, 2);
    const float inv0 = 1.0f / den0;
    const float inv1 = 1.0f / den1;

    float* o0 = out + (size_t)((bb << 12) + iA) * (NH * FO) + hh * FO;
    float* o1 = o0 + (size_t)8 * (NH * FO);
#pragma unroll
    for (int nt = 0; nt < 8; nt++) {
        const int col = nt * 8 + q2;
        float2 bv = *(const float2*)&bias[hh * FO + col];
        float v00 = fmaf(acc[nt][0], inv0, bv.x);
        float v01 = fmaf(acc[nt][1], inv0, bv.y);
        float v10 = fmaf(acc[nt][2], inv1, bv.x);
        float v11 = fmaf(acc[nt][3], inv1, bv.y);
        v00 = v00 > 0.0f ? v00 : expm1f(v00);
        v01 = v01 > 0.0f ? v01 : expm1f(v01);
        v10 = v10 > 0.0f ? v10 : expm1f(v10);
        v11 = v11 > 0.0f ? v11 : expm1f(v11);
        *(float2*)&o0[col] = make_float2(v00, v01);
        *(float2*)&o1[col] = make_float2(v10, v11);
    }
}

// ---------------- launch ----------------
extern "C" void kernel_launch(void* const* d_in, const int* in_sizes, int n_in,
                              void* d_out, int out_size) {
    const int*   adj = (const int*)  d_in[0];  // (B,N,N) int32
    const float* h   = (const float*)d_in[1];  // (B,N,256)
    const float* W   = (const float*)d_in[2];  // (256,64)
    const float* Wl  = (const float*)d_in[3];  // (4,64)
    const float* Wr  = (const float*)d_in[4];  // (4,64)
    const float* bia = (const float*)d_in[5];  // (64,)
    float* out = (float*)d_out;                // (B,N,256)

    k_pack<<<1024, 256>>>(adj);
    k_gemm_xw<<<ROWS / 64, 256>>>(h, W);
    k_coef<<<ROWS / 4, 128>>>(Wl, Wr);
    k_split<<<ROWS / 64, 256>>>();
    k_attn<<<Bdim * (Ndim / TI), 256>>>(bia, out);
}

// round 9
// speedup vs baseline: 2.9593x; 1.1337x over previous
#include <cuda_runtime.h>
#include <cuda_bf16.h>

// Problem constants (fixed by the reference)
#define Bdim 2
#define Ndim 4096
#define FIN  256
#define FO   64
#define NH   4
#define ROWS (Bdim * Ndim)   // 8192

#define TI 32               // i-rows per block
#define TJ 32               // j-cols per tile
#define NT (Ndim / TJ)      // 128 j-tiles

// -------- device scratch (no allocation allowed) --------
__device__ float         g_X   [ROWS * FO];          // (B,N,64) = h @ W
__device__ float2        g_elEF[ROWS * NH];          // {exp(el), exp(0.2*el)}
__device__ float2        g_erEF[ROWS * NH];          // {exp(er), exp(0.2*er)}  (j,h) contiguous
__device__ __nv_bfloat16 g_XTh[ROWS * FO];           // X^T hi, [b][n(64)][j(4096)]
__device__ __nv_bfloat16 g_XTl[ROWS * FO];           // X^T lo
__device__ unsigned      g_mask[ROWS * NT];          // adjacency bitmask [row][jword]

// -------- helpers --------
__device__ __forceinline__ unsigned pack_bf16x2(float lo, float hi) {
    unsigned r;
    asm("cvt.rn.bf16x2.f32 %0, %1, %2;" : "=r"(r) : "f"(hi), "f"(lo));
    return r;
}
__device__ __forceinline__ float bf16lo_f(unsigned v) { return __uint_as_float(v << 16); }
__device__ __forceinline__ float bf16hi_f(unsigned v) { return __uint_as_float(v & 0xffff0000u); }

__device__ __forceinline__ void mma_bf16(float* c, unsigned a0, unsigned a1,
                                         unsigned a2, unsigned a3,
                                         unsigned b0, unsigned b1) {
    asm volatile(
        "mma.sync.aligned.m16n8k16.row.col.f32.bf16.bf16.f32 "
        "{%0,%1,%2,%3}, {%4,%5,%6,%7}, {%8,%9}, {%0,%1,%2,%3};"
        : "+f"(c[0]), "+f"(c[1]), "+f"(c[2]), "+f"(c[3])
        : "r"(a0), "r"(a1), "r"(a2), "r"(a3), "r"(b0), "r"(b1));
}

__device__ __forceinline__ void cp16(unsigned saddr, const void* g) {
    asm volatile("cp.async.cg.shared.global [%0], [%1], 16;\n"
                 :: "r"(saddr), "l"(g));
}
__device__ __forceinline__ void cp_commit() {
    asm volatile("cp.async.commit_group;\n" ::);
}
__device__ __forceinline__ void cp_wait0() {
    asm volatile("cp.async.wait_group 0;\n" ::);
}

// ---------------- Kernel A: X = h @ W, fused transpose + bf16 hi/lo split ----
__global__ __launch_bounds__(256) void k_gemm_xw(const float* __restrict__ h,
                                                 const float* __restrict__ W) {
    __shared__ float sh[64][33];
    __shared__ float sw[32][64];
    __shared__ float ts[64][65];   // staging tile [row_local][feature]

    const int tid  = threadIdx.x;
    const int tx   = tid & 15;
    const int ty   = tid >> 4;
    const int row0 = blockIdx.x * 64;

    float acc[4][4];
#pragma unroll
    for (int i = 0; i < 4; i++)
#pragma unroll
        for (int j = 0; j < 4; j++) acc[i][j] = 0.0f;

    for (int k0 = 0; k0 < FIN; k0 += 32) {
        __syncthreads();
#pragma unroll
        for (int m = 0; m < 8; m++) {
            int idx = tid + 256 * m;
            sh[idx >> 5][idx & 31] =
                h[(size_t)(row0 + (idx >> 5)) * FIN + k0 + (idx & 31)];
            sw[idx >> 6][idx & 63] = W[(size_t)(k0 + (idx >> 6)) * FO + (idx & 63)];
        }
        __syncthreads();
#pragma unroll
        for (int kk = 0; kk < 32; kk++) {
            float a[4];
#pragma unroll
            for (int i = 0; i < 4; i++) a[i] = sh[ty * 4 + i][kk];
            float4 bb = *(const float4*)&sw[kk][tx * 4];
#pragma unroll
            for (int i = 0; i < 4; i++) {
                acc[i][0] = fmaf(a[i], bb.x, acc[i][0]);
                acc[i][1] = fmaf(a[i], bb.y, acc[i][1]);
                acc[i][2] = fmaf(a[i], bb.z, acc[i][2]);
                acc[i][3] = fmaf(a[i], bb.w, acc[i][3]);
            }
        }
    }
    // write g_X (row-major, used by k_coef) + stash tile as [row][feature]
#pragma unroll
    for (int i = 0; i < 4; i++) {
        *(float4*)&g_X[(size_t)(row0 + ty * 4 + i) * FO + tx * 4] =
            make_float4(acc[i][0], acc[i][1], acc[i][2], acc[i][3]);
#pragma unroll
        for (int j = 0; j < 4; j++) ts[ty * 4 + i][tx * 4 + j] = acc[i][j];  // FIXED
    }
    __syncthreads();

    // emit X^T bf16 hi/lo: feature n = tid>>2 owns 16 consecutive j's
    const int n    = tid >> 2;
    const int part = tid & 3;
    const int b    = row0 >> 12;
    const int jloc = row0 & 4095;
    size_t base = ((size_t)(b * 64 + n) * Ndim + jloc + part * 16);
#pragma unroll
    for (int jj = 0; jj < 16; jj += 2) {
        float v0 = ts[part * 16 + jj][n];
        float v1 = ts[part * 16 + jj + 1][n];
        unsigned hpack = pack_bf16x2(v0, v1);
        float r0f = v0 - bf16lo_f(hpack);
        float r1f = v1 - bf16hi_f(hpack);
        unsigned lpack = pack_bf16x2(r0f, r1f);
        *(unsigned*)((char*)g_XTh + (base + jj) * 2) = hpack;
        *(unsigned*)((char*)g_XTl + (base + jj) * 2) = lpack;
    }
}

// ---------------- Kernel B: attention coefficients -> exp pairs ----------------
__global__ __launch_bounds__(128) void k_coef(const float* __restrict__ Wl,
                                              const float* __restrict__ Wr) {
    const int row  = blockIdx.x * 4 + (threadIdx.x >> 5);
    const int lane = threadIdx.x & 31;
    float2 x2 = *(const float2*)&g_X[(size_t)row * FO + lane * 2];
#pragma unroll
    for (int hh = 0; hh < NH; hh++) {
        float2 wl = *(const float2*)&Wl[hh * FO + lane * 2];
        float v = x2.x * wl.x + x2.y * wl.y;
#pragma unroll
        for (int o = 16; o > 0; o >>= 1) v += __shfl_xor_sync(0xffffffffu, v, o);
        float2 wr = *(const float2*)&Wr[hh * FO + lane * 2];
        float u = x2.x * wr.x + x2.y * wr.y;
#pragma unroll
        for (int o = 16; o > 0; o >>= 1) u += __shfl_xor_sync(0xffffffffu, u, o);
        if (lane == 0) {
            g_elEF[row * NH + hh] = make_float2(__expf(v), __expf(0.2f * v));
            g_erEF[row * NH + hh] = make_float2(__expf(u), __expf(0.2f * u));
        }
    }
}

// ---------------- Kernel D: pack adjacency to bitmasks ----------------
__global__ __launch_bounds__(256) void k_pack(const int* __restrict__ adj) {
    const int lane = threadIdx.x & 31;
    const int wgl  = (blockIdx.x * 8) + (threadIdx.x >> 5);
#pragma unroll 4
    for (int it = 0; it < 128; it++) {
        int word = wgl + it * 8192;
        int v = adj[(size_t)word * 32 + lane];
        unsigned m = __ballot_sync(0xffffffffu, v != 0);
        if (lane == 0) g_mask[word] = m;
    }
}

// ---------------- Kernel E: fused attention + PV, cp.async double-buffered ----
#define XS_STRIDE 80     // bytes per n-row (64B data + 16B pad) -> conflict-free
#define XS_BYTES  (64 * XS_STRIDE)   // 5120 per stage
__global__ __launch_bounds__(256, 2) void k_attn(const float* __restrict__ bias,
                                                 float* __restrict__ out) {
    __shared__ __align__(16) unsigned char sXh[2][XS_BYTES];
    __shared__ __align__(16) unsigned char sXl[2][XS_BYTES];
    __shared__ __align__(16) float2 erS[2][TJ * NH];   // 1KB per stage, contiguous

    const int tid  = threadIdx.x;
    const int w    = tid >> 5;
    const int lane = tid & 31;
    const int g    = lane >> 2;      // 0..7
    const int q    = lane & 3;       // 0..3
    const int q2   = q * 2;

    const int bb = blockIdx.x >> 7;
    const int i0 = (blockIdx.x & 127) * TI;
    const int hh = w >> 1;
    const int iA = i0 + (w & 1) * 16 + g;        // rows iA and iA+8

    const float2 efA = g_elEF[((bb << 12) + iA) * NH + hh];
    const float2 efB = g_elEF[((bb << 12) + iA + 8) * NH + hh];
    const unsigned* mrowA = &g_mask[(size_t)((bb << 12) + iA) * NT];
    const unsigned* mrowB = &g_mask[(size_t)((bb << 12) + iA + 8) * NT];

    float acc[8][4];
#pragma unroll
    for (int n = 0; n < 8; n++)
#pragma unroll
        for (int k = 0; k < 4; k++) acc[n][k] = 0.0f;
    float den0 = 0.0f, den1 = 0.0f;

    const char* XThB = (const char*)(g_XTh + (size_t)bb * 64 * Ndim);
    const char* XTlB = (const char*)(g_XTl + (size_t)bb * 64 * Ndim);
    const char* erBp = (const char*)(g_erEF + (size_t)(bb << 12) * NH);

    // staging mapping
    const int sn = tid >> 2;
    const int sp = tid & 3;
    const unsigned aXh = (unsigned)__cvta_generic_to_shared(&sXh[0][0]);
    const unsigned aXl = (unsigned)__cvta_generic_to_shared(&sXl[0][0]);
    const unsigned aEr = (unsigned)__cvta_generic_to_shared(&erS[0][0]);
    const unsigned dstOff = sn * XS_STRIDE + sp * 16;
    const size_t   srcRow = (size_t)sn * Ndim + sp * 8;   // + j0, in elements

    // prologue: issue tile 0 into stage 0
    {
        size_t sb = srcRow * 2;       // bytes (j0 = 0)
        cp16(aXh + dstOff, XThB + sb);
        cp16(aXl + dstOff, XTlB + sb);
        if (tid < 64) cp16(aEr + tid * 16, erBp + tid * 16);
        cp_commit();
    }

    unsigned mwA = mrowA[0];
    unsigned mwB = mrowB[0];

    for (int jt = 0; jt < NT; jt++) {
        const int st = jt & 1;
        cp_wait0();            // tile jt resident (issuing thread)
        __syncthreads();       // visible to all; all done computing tile jt-1

        // issue tile jt+1 into the other stage (overlaps compute below)
        if (jt + 1 < NT) {
            size_t sb = (srcRow + (size_t)(jt + 1) * TJ) * 2;
            unsigned so = (st ^ 1) * XS_BYTES + dstOff;
            cp16(aXh + so, XThB + sb);
            cp16(aXl + so, XTlB + sb);
            if (tid < 64)
                cp16(aEr + (st ^ 1) * (TJ * NH * 8) + tid * 16,
                     erBp + (size_t)(jt + 1) * (TJ * NH * 8) + tid * 16);
        }
        cp_commit();

        // prefetch next mask words (consumed next iter)
        unsigned nmwA = 0, nmwB = 0;
        if (jt + 1 < NT) { nmwA = mrowA[jt + 1]; nmwB = mrowB[jt + 1]; }

        const float2* er = erS[st];
        const unsigned char* xh = sXh[st];
        const unsigned char* xl = sXl[st];

#pragma unroll
        for (int kt = 0; kt < 2; kt++) {
            const int cb = kt * 16 + q2;
            float2 e0 = er[(cb)     * NH + hh];
            float2 e1 = er[(cb + 1) * NH + hh];
            float2 e2 = er[(cb + 8) * NH + hh];
            float2 e3 = er[(cb + 9) * NH + hh];

            unsigned msA = mwA >> cb;
            unsigned msB = mwB >> cb;

            float pA0 = (msA & 1u)   ? fmaxf(efA.x * e0.x, efA.y * e0.y) : 0.0f;
            float pA1 = (msA & 2u)   ? fmaxf(efA.x * e1.x, efA.y * e1.y) : 0.0f;
            float pA2 = (msA & 256u) ? fmaxf(efA.x * e2.x, efA.y * e2.y) : 0.0f;
            float pA3 = (msA & 512u) ? fmaxf(efA.x * e3.x, efA.y * e3.y) : 0.0f;
            float pB0 = (msB & 1u)   ? fmaxf(efB.x * e0.x, efB.y * e0.y) : 0.0f;
            float pB1 = (msB & 2u)   ? fmaxf(efB.x * e1.x, efB.y * e1.y) : 0.0f;
            float pB2 = (msB & 256u) ? fmaxf(efB.x * e2.x, efB.y * e2.y) : 0.0f;
            float pB3 = (msB & 512u) ? fmaxf(efB.x * e3.x, efB.y * e3.y) : 0.0f;

            den0 += (pA0 + pA1) + (pA2 + pA3);
            den1 += (pB0 + pB1) + (pB2 + pB3);

            unsigned aH0 = pack_bf16x2(pA0, pA1);
            unsigned aH1 = pack_bf16x2(pB0, pB1);
            unsigned aH2 = pack_bf16x2(pA2, pA3);
            unsigned aH3 = pack_bf16x2(pB2, pB3);
            unsigned aL0 = pack_bf16x2(pA0 - bf16lo_f(aH0), pA1 - bf16hi_f(aH0));
            unsigned aL1 = pack_bf16x2(pB0 - bf16lo_f(aH1), pB1 - bf16hi_f(aH1));
            unsigned aL2 = pack_bf16x2(pA2 - bf16lo_f(aH2), pA3 - bf16hi_f(aH2));
            unsigned aL3 = pack_bf16x2(pB2 - bf16lo_f(aH3), pB3 - bf16hi_f(aH3));

            const int boff = g * XS_STRIDE + kt * 32 + q * 4;
#pragma unroll
            for (int nt = 0; nt < 8; nt++) {
                const int o = nt * 8 * XS_STRIDE + boff;
                unsigned bh0 = *(const unsigned*)(xh + o);
                unsigned bh1 = *(const unsigned*)(xh + o + 16);
                unsigned bl0 = *(const unsigned*)(xl + o);
                unsigned bl1 = *(const unsigned*)(xl + o + 16);
                mma_bf16(acc[nt], aH0, aH1, aH2, aH3, bh0, bh1);
                mma_bf16(acc[nt], aH0, aH1, aH2, aH3, bl0, bl1);
                mma_bf16(acc[nt], aL0, aL1, aL2, aL3, bh0, bh1);
            }
        }
        mwA = nmwA;
        mwB = nmwB;
    }

    // reduce denominators across the 4 lanes of each row group
    den0 += __shfl_xor_sync(0xffffffffu, den0, 1);
    den0 += __shfl_xor_sync(0xffffffffu, den0, 2);
    den1 += __shfl_xor_sync(0xffffffffu, den1, 1);
    den1 += __shfl_xor_sync(0xffffffffu, den1, 2);
    const float inv0 = 1.0f / den0;
    const float inv1 = 1.0f / den1;

    float* o0 = out + (size_t)((bb << 12) + iA) * (NH * FO) + hh * FO;
    float* o1 = o0 + (size_t)8 * (NH * FO);
#pragma unroll
    for (int nt = 0; nt < 8; nt++) {
        const int col = nt * 8 + q2;
        float2 bv = *(const float2*)&bias[hh * FO + col];
        float v00 = fmaf(acc[nt][0], inv0, bv.x);
        float v01 = fmaf(acc[nt][1], inv0, bv.y);
        float v10 = fmaf(acc[nt][2], inv1, bv.x);
        float v11 = fmaf(acc[nt][3], inv1, bv.y);
        v00 = v00 > 0.0f ? v00 : expm1f(v00);
        v01 = v01 > 0.0f ? v01 : expm1f(v01);
        v10 = v10 > 0.0f ? v10 : expm1f(v10);
        v11 = v11 > 0.0f ? v11 : expm1f(v11);
        *(float2*)&o0[col] = make_float2(v00, v01);
        *(float2*)&o1[col] = make_float2(v10, v11);
    }
}

// ---------------- launch ----------------
extern "C" void kernel_launch(void* const* d_in, const int* in_sizes, int n_in,
                              void* d_out, int out_size) {
    const int*   adj = (const int*)  d_in[0];  // (B,N,N) int32
    const float* h   = (const float*)d_in[1];  // (B,N,256)
    const float* W   = (const float*)d_in[2];  // (256,64)
    const float* Wl  = (const float*)d_in[3];  // (4,64)
    const float* Wr  = (const float*)d_in[4];  // (4,64)
    const float* bia = (const float*)d_in[5];  // (64,)
    float* out = (float*)d_out;                // (B,N,256)

    k_pack<<<1024, 256>>>(adj);
    k_gemm_xw<<<ROWS / 64, 256>>>(h, W);
    k_coef<<<ROWS / 4, 128>>>(Wl, Wr);
    k_attn<<<Bdim * (Ndim / TI), 256>>>(bia, out);
}